// round 1
// baseline (speedup 1.0000x reference)
#include <cuda_runtime.h>
#include <math.h>

// Problem shape (fixed by the dataset).
#define BATCH 1024
#define NBG   256
#define DIM   512
#define DIM4  (DIM/4)              // 128 float4 per row

#define ROWS_PER_WARP   8
#define WARPS_PER_BLOCK 8
#define THREADS_PER_BLOCK (WARPS_PER_BLOCK*32)
#define ROWS_PER_BLOCK  (ROWS_PER_WARP*WARPS_PER_BLOCK)   // 64
#define BG_BLOCKS ((BATCH*NBG)/ROWS_PER_BLOCK)            // 4096

#define POS_BLOCKS (BATCH/WARPS_PER_BLOCK)                // 128

// Deterministic partial sums (no atomics -> bitwise identical every replay).
__device__ float g_partial_bg[BG_BLOCKS];
__device__ float g_partial_pos[POS_BLOCKS];

__device__ __forceinline__ float warp_sum(float v) {
    #pragma unroll
    for (int o = 16; o > 0; o >>= 1)
        v += __shfl_xor_sync(0xFFFFFFFFu, v, o);
    return v;
}

// ---------------------------------------------------------------------------
// Kernel P: per-batch positive logit. One warp per batch row.
// partial_pos[block] = sum over 8 rows of exp(dot(img_hat[b], fg_pro[b]))
// ---------------------------------------------------------------------------
__global__ void __launch_bounds__(THREADS_PER_BLOCK)
pos_kernel(const float* __restrict__ img, const float* __restrict__ fg)
{
    const int warp = threadIdx.x >> 5;
    const int lane = threadIdx.x & 31;
    const int b = blockIdx.x * WARPS_PER_BLOCK + warp;

    const float4* irow = reinterpret_cast<const float4*>(img + (size_t)b * DIM);
    const float4* frow = reinterpret_cast<const float4*>(fg  + (size_t)b * DIM);

    float nrm = 0.f, dotp = 0.f;
    #pragma unroll
    for (int i = 0; i < 4; i++) {
        float4 iv = irow[lane + 32*i];
        float4 fv = frow[lane + 32*i];
        nrm  += iv.x*iv.x + iv.y*iv.y + iv.z*iv.z + iv.w*iv.w;
        dotp += iv.x*fv.x + iv.y*fv.y + iv.z*fv.z + iv.w*fv.w;
    }
    nrm  = warp_sum(nrm);
    dotp = warp_sum(dotp);
    float e = __expf(dotp * rsqrtf(nrm));

    __shared__ float s[WARPS_PER_BLOCK];
    if (lane == 0) s[warp] = e;
    __syncthreads();
    if (threadIdx.x == 0) {
        float acc = 0.f;
        #pragma unroll
        for (int w = 0; w < WARPS_PER_BLOCK; w++) acc += s[w];
        g_partial_pos[blockIdx.x] = acc;
    }
}

// ---------------------------------------------------------------------------
// Kernel BG: the 512 MB stream. One warp per group of 8 bg rows (same b).
// ---------------------------------------------------------------------------
__global__ void __launch_bounds__(THREADS_PER_BLOCK)
bg_kernel(const float* __restrict__ img, const float* __restrict__ bg)
{
    const int warp = threadIdx.x >> 5;
    const int lane = threadIdx.x & 31;
    // Global row index into the flattened [BATCH*NBG, DIM] bg matrix.
    const int rowBase = blockIdx.x * ROWS_PER_BLOCK + warp * ROWS_PER_WARP;
    const int b = rowBase / NBG;   // ROWS_PER_BLOCK (64) divides NBG (256): one b per block

    // img row resident in registers for the whole warp's 8 rows.
    const float4* irow = reinterpret_cast<const float4*>(img + (size_t)b * DIM);
    float4 iv[4];
    float nrm = 0.f;
    #pragma unroll
    for (int i = 0; i < 4; i++) {
        iv[i] = irow[lane + 32*i];
        nrm += iv[i].x*iv[i].x + iv[i].y*iv[i].y + iv[i].z*iv[i].z + iv[i].w*iv[i].w;
    }
    nrm = warp_sum(nrm);
    const float rinv = rsqrtf(nrm);

    const float4* rowp = reinterpret_cast<const float4*>(bg) + (size_t)rowBase * DIM4;

    float acc = 0.f;
    #pragma unroll
    for (int r = 0; r < ROWS_PER_WARP; r++) {
        const float4* row = rowp + (size_t)r * DIM4;
        float d = 0.f;
        #pragma unroll
        for (int i = 0; i < 4; i++) {
            float4 v = row[lane + 32*i];
            d += v.x*iv[i].x + v.y*iv[i].y + v.z*iv[i].z + v.w*iv[i].w;
        }
        d = warp_sum(d);
        acc += __expf(d * rinv);   // replicated across lanes; lane 0 consumes
    }

    __shared__ float s[WARPS_PER_BLOCK];
    if (lane == 0) s[warp] = acc;
    __syncthreads();
    if (threadIdx.x == 0) {
        float t = 0.f;
        #pragma unroll
        for (int w = 0; w < WARPS_PER_BLOCK; w++) t += s[w];
        g_partial_bg[blockIdx.x] = t;
    }
}

// ---------------------------------------------------------------------------
// Kernel F: final reduction + loss. One block.
// out = -log(pos / (pos + bg)) = log1p(bg / pos)
// ---------------------------------------------------------------------------
__global__ void __launch_bounds__(256)
final_kernel(float* __restrict__ out)
{
    __shared__ float sbg[256];
    __shared__ float spos[256];
    const int t = threadIdx.x;

    float a = 0.f;
    for (int i = t; i < BG_BLOCKS; i += 256) a += g_partial_bg[i];
    float p = 0.f;
    for (int i = t; i < POS_BLOCKS; i += 256) p += g_partial_pos[i];
    sbg[t] = a; spos[t] = p;
    __syncthreads();
    #pragma unroll
    for (int s = 128; s > 0; s >>= 1) {
        if (t < s) { sbg[t] += sbg[t+s]; spos[t] += spos[t+s]; }
        __syncthreads();
    }
    if (t == 0) {
        float bgsum = sbg[0], possum = spos[0];
        out[0] = log1pf(bgsum / possum);
    }
}

extern "C" void kernel_launch(void* const* d_in, const int* in_sizes, int n_in,
                              void* d_out, int out_size)
{
    const float* fg_img = (const float*)d_in[0];   // [B, D]
    const float* fg_pro = (const float*)d_in[1];   // [B, D]
    const float* bg_pro = (const float*)d_in[2];   // [B, N, D]
    float* out = (float*)d_out;

    pos_kernel<<<POS_BLOCKS, THREADS_PER_BLOCK>>>(fg_img, fg_pro);
    bg_kernel<<<BG_BLOCKS, THREADS_PER_BLOCK>>>(fg_img, bg_pro);
    final_kernel<<<1, 256>>>(out);
}

// round 2
// speedup vs baseline: 1.0708x; 1.0708x over previous
#include <cuda_runtime.h>
#include <math.h>

// Problem shape (fixed by the dataset).
#define BATCH 1024
#define NBG   256
#define DIM   512
#define DIM4  (DIM/4)              // 128 float4 per row

#define ROWS_PER_WARP   8
#define WARPS_PER_BLOCK 8
#define THREADS_PER_BLOCK (WARPS_PER_BLOCK*32)
#define ROWS_PER_BLOCK  (ROWS_PER_WARP*WARPS_PER_BLOCK)   // 64
#define BG_BLOCKS ((BATCH*NBG)/ROWS_PER_BLOCK)            // 4096
#define BLOCKS_PER_B (NBG/ROWS_PER_BLOCK)                 // 4

// Deterministic partial sums (no atomics -> bitwise identical every replay).
__device__ float g_partial_bg[BG_BLOCKS];
__device__ float g_partial_pos[BATCH];

__device__ __forceinline__ float warp_sum(float v) {
    #pragma unroll
    for (int o = 16; o > 0; o >>= 1)
        v += __shfl_xor_sync(0xFFFFFFFFu, v, o);
    return v;
}

// ---------------------------------------------------------------------------
// Fused kernel: streams bg (512 MB), computes per-row exp(logit) sums.
// Blocks whose row range starts at b*NBG also compute the positive logit
// for batch b (warp 0), reusing the register-resident img row + rinv.
// ---------------------------------------------------------------------------
__global__ void __launch_bounds__(THREADS_PER_BLOCK)
bg_kernel(const float* __restrict__ img, const float* __restrict__ fg,
          const float* __restrict__ bg)
{
    const int warp = threadIdx.x >> 5;
    const int lane = threadIdx.x & 31;
    const int rowBase = blockIdx.x * ROWS_PER_BLOCK + warp * ROWS_PER_WARP;
    const int b = blockIdx.x >> 2;   // BLOCKS_PER_B == 4, 64 rows/block within one b

    // img row resident in registers for the whole warp's 8 rows.
    const float4* irow = reinterpret_cast<const float4*>(img + (size_t)b * DIM);
    float4 iv[4];
    float nrm = 0.f;
    #pragma unroll
    for (int i = 0; i < 4; i++) {
        iv[i] = irow[lane + 32*i];
        nrm += iv[i].x*iv[i].x + iv[i].y*iv[i].y + iv[i].z*iv[i].z + iv[i].w*iv[i].w;
    }
    nrm = warp_sum(nrm);
    const float rinv = rsqrtf(nrm);

    const float4* rowp = reinterpret_cast<const float4*>(bg) + (size_t)rowBase * DIM4;

    // Per-lane partial dot for each of the 8 rows (streaming loads).
    float d[ROWS_PER_WARP];
    #pragma unroll
    for (int r = 0; r < ROWS_PER_WARP; r++) {
        const float4* row = rowp + (size_t)r * DIM4;
        float acc0 = 0.f;
        #pragma unroll
        for (int i = 0; i < 4; i++) {
            float4 v = __ldcs(&row[lane + 32*i]);
            acc0 += v.x*iv[i].x + v.y*iv[i].y + v.z*iv[i].z + v.w*iv[i].w;
        }
        d[r] = acc0;
    }

    // Folded butterfly: reduce 8 values across 32 lanes in 9 shuffles.
    // Stage xor16: fold 8 -> 4 (slot i holds row i + 4*bit16(lane)).
    #pragma unroll
    for (int i = 0; i < 4; i++) {
        float a  = (lane & 16) ? d[i+4] : d[i];
        float bv = (lane & 16) ? d[i]   : d[i+4];
        d[i] = a + __shfl_xor_sync(0xFFFFFFFFu, bv, 16);
    }
    // Stage xor8: fold 4 -> 2 (slot i holds row i + 2*bit8 + 4*bit16).
    #pragma unroll
    for (int i = 0; i < 2; i++) {
        float a  = (lane & 8) ? d[i+2] : d[i];
        float bv = (lane & 8) ? d[i]   : d[i+2];
        d[i] = a + __shfl_xor_sync(0xFFFFFFFFu, bv, 8);
    }
    // Stage xor4: fold 2 -> 1 (value for row = bit4 + 2*bit8 + 4*bit16).
    float v;
    {
        float a  = (lane & 4) ? d[1] : d[0];
        float bv = (lane & 4) ? d[0] : d[1];
        v = a + __shfl_xor_sync(0xFFFFFFFFu, bv, 4);
    }
    // Finish the remaining 4 lanes (offsets 2, 1).
    v += __shfl_xor_sync(0xFFFFFFFFu, v, 2);
    v += __shfl_xor_sync(0xFFFFFFFFu, v, 1);
    // Each lane now holds the full dot for its row (replicated x4).
    float e = __expf(v * rinv);
    float acc = ((lane & 3) == 0) ? e : 0.f;

    // Positive logit for batch b: warp 0 of the first block of each b.
    if (((blockIdx.x & 3) == 0) && warp == 0) {
        const float4* frow = reinterpret_cast<const float4*>(fg + (size_t)b * DIM);
        float dp = 0.f;
        #pragma unroll
        for (int i = 0; i < 4; i++) {
            float4 fv = frow[lane + 32*i];
            dp += fv.x*iv[i].x + fv.y*iv[i].y + fv.z*iv[i].z + fv.w*iv[i].w;
        }
        dp = warp_sum(dp);
        if (lane == 0) g_partial_pos[b] = __expf(dp * rinv);
    }

    // Block reduction of the 8 masked exps per warp.
    acc = warp_sum(acc);
    __shared__ float s[WARPS_PER_BLOCK];
    if (lane == 0) s[warp] = acc;
    __syncthreads();
    if (threadIdx.x == 0) {
        float t = 0.f;
        #pragma unroll
        for (int w = 0; w < WARPS_PER_BLOCK; w++) t += s[w];
        g_partial_bg[blockIdx.x] = t;
    }
}

// ---------------------------------------------------------------------------
// Final reduction + loss. One block.
// out = -log(pos / (pos + bg)) = log1p(bg / pos)
// ---------------------------------------------------------------------------
__global__ void __launch_bounds__(256)
final_kernel(float* __restrict__ out)
{
    __shared__ float sbg[256];
    __shared__ float spos[256];
    const int t = threadIdx.x;

    float a = 0.f;
    for (int i = t; i < BG_BLOCKS; i += 256) a += g_partial_bg[i];
    float p = 0.f;
    for (int i = t; i < BATCH; i += 256) p += g_partial_pos[i];
    sbg[t] = a; spos[t] = p;
    __syncthreads();
    #pragma unroll
    for (int s = 128; s > 0; s >>= 1) {
        if (t < s) { sbg[t] += sbg[t+s]; spos[t] += spos[t+s]; }
        __syncthreads();
    }
    if (t == 0) {
        out[0] = log1pf(sbg[0] / spos[0]);
    }
}

extern "C" void kernel_launch(void* const* d_in, const int* in_sizes, int n_in,
                              void* d_out, int out_size)
{
    const float* fg_img = (const float*)d_in[0];   // [B, D]
    const float* fg_pro = (const float*)d_in[1];   // [B, D]
    const float* bg_pro = (const float*)d_in[2];   // [B, N, D]
    float* out = (float*)d_out;

    bg_kernel<<<BG_BLOCKS, THREADS_PER_BLOCK>>>(fg_img, fg_pro, bg_pro);
    final_kernel<<<1, 256>>>(out);
}

// round 3
// speedup vs baseline: 1.0992x; 1.0265x over previous
#include <cuda_runtime.h>
#include <math.h>

// Problem shape (fixed by the dataset).
#define BATCH 1024
#define NBG   256
#define DIM   512
#define DIM4  (DIM/4)              // 128 float4 per row

#define ROWS_PER_WARP   8
#define WARPS_PER_BLOCK 8
#define THREADS_PER_BLOCK (WARPS_PER_BLOCK*32)
#define ROWS_PER_BLOCK  (ROWS_PER_WARP*WARPS_PER_BLOCK)   // 64
#define BG_BLOCKS ((BATCH*NBG)/ROWS_PER_BLOCK)            // 4096

// Deterministic partial sums (no atomics in the summation -> bitwise
// identical every replay; the atomic below only ELECTS the reducing block).
__device__ float g_partial_bg[BG_BLOCKS];
__device__ float g_partial_pos[BATCH];
__device__ unsigned int g_done_count;   // zero-init at module load; reset each launch

__device__ __forceinline__ float warp_sum(float v) {
    #pragma unroll
    for (int o = 16; o > 0; o >>= 1)
        v += __shfl_xor_sync(0xFFFFFFFFu, v, o);
    return v;
}

// ---------------------------------------------------------------------------
// Fused kernel: streams bg (512 MB), computes per-row exp(logit) sums,
// positive logits (warp 0 of every 4th block), and the final loss in the
// last-to-finish block.
// ---------------------------------------------------------------------------
__global__ void __launch_bounds__(THREADS_PER_BLOCK)
bg_kernel(const float* __restrict__ img, const float* __restrict__ fg,
          const float* __restrict__ bg, float* __restrict__ out)
{
    const int warp = threadIdx.x >> 5;
    const int lane = threadIdx.x & 31;
    const int rowBase = blockIdx.x * ROWS_PER_BLOCK + warp * ROWS_PER_WARP;
    const int b = blockIdx.x >> 2;   // 4 blocks per batch row; 64 rows/block in one b

    // img row resident in registers for the whole warp's 8 rows.
    const float4* irow = reinterpret_cast<const float4*>(img + (size_t)b * DIM);
    float4 iv[4];
    float nrm = 0.f;
    #pragma unroll
    for (int i = 0; i < 4; i++) {
        iv[i] = irow[lane + 32*i];
        nrm += iv[i].x*iv[i].x + iv[i].y*iv[i].y + iv[i].z*iv[i].z + iv[i].w*iv[i].w;
    }
    nrm = warp_sum(nrm);
    const float rinv = rsqrtf(nrm);

    const float4* rowp = reinterpret_cast<const float4*>(bg) + (size_t)rowBase * DIM4;

    // Per-lane partial dot for each of the 8 rows (streaming loads).
    float d[ROWS_PER_WARP];
    #pragma unroll
    for (int r = 0; r < ROWS_PER_WARP; r++) {
        const float4* row = rowp + (size_t)r * DIM4;
        float acc0 = 0.f;
        #pragma unroll
        for (int i = 0; i < 4; i++) {
            float4 v = __ldcs(&row[lane + 32*i]);
            acc0 += v.x*iv[i].x + v.y*iv[i].y + v.z*iv[i].z + v.w*iv[i].w;
        }
        d[r] = acc0;
    }

    // Folded butterfly: reduce 8 row-dots across 32 lanes in 9 shuffles.
    #pragma unroll
    for (int i = 0; i < 4; i++) {
        float a  = (lane & 16) ? d[i+4] : d[i];
        float bv = (lane & 16) ? d[i]   : d[i+4];
        d[i] = a + __shfl_xor_sync(0xFFFFFFFFu, bv, 16);
    }
    #pragma unroll
    for (int i = 0; i < 2; i++) {
        float a  = (lane & 8) ? d[i+2] : d[i];
        float bv = (lane & 8) ? d[i]   : d[i+2];
        d[i] = a + __shfl_xor_sync(0xFFFFFFFFu, bv, 8);
    }
    float v;
    {
        float a  = (lane & 4) ? d[1] : d[0];
        float bv = (lane & 4) ? d[0] : d[1];
        v = a + __shfl_xor_sync(0xFFFFFFFFu, bv, 4);
    }
    v += __shfl_xor_sync(0xFFFFFFFFu, v, 2);
    v += __shfl_xor_sync(0xFFFFFFFFu, v, 1);
    float e = __expf(v * rinv);
    float acc = ((lane & 3) == 0) ? e : 0.f;

    // Positive logit for batch b: warp 0 of the first block of each b.
    if (((blockIdx.x & 3) == 0) && warp == 0) {
        const float4* frow = reinterpret_cast<const float4*>(fg + (size_t)b * DIM);
        float dp = 0.f;
        #pragma unroll
        for (int i = 0; i < 4; i++) {
            float4 fv = frow[lane + 32*i];
            dp += fv.x*iv[i].x + fv.y*iv[i].y + fv.z*iv[i].z + fv.w*iv[i].w;
        }
        dp = warp_sum(dp);
        if (lane == 0) g_partial_pos[b] = __expf(dp * rinv);
    }

    // Block reduction of the 8 masked exps per warp.
    acc = warp_sum(acc);
    __shared__ float s[WARPS_PER_BLOCK];
    __shared__ bool s_last;
    if (lane == 0) s[warp] = acc;
    __syncthreads();
    if (threadIdx.x == 0) {
        float t = 0.f;
        #pragma unroll
        for (int w = 0; w < WARPS_PER_BLOCK; w++) t += s[w];
        g_partial_bg[blockIdx.x] = t;
        __threadfence();
        unsigned int c = atomicAdd(&g_done_count, 1u);
        s_last = (c == (unsigned int)(BG_BLOCKS - 1));
    }
    __syncthreads();

    // Last-to-finish block performs the final deterministic reduction.
    if (s_last) {
        const int t = threadIdx.x;
        const float4* pbg  = reinterpret_cast<const float4*>(g_partial_bg);
        const float4* ppos = reinterpret_cast<const float4*>(g_partial_pos);
        float a = 0.f;
        #pragma unroll
        for (int i = 0; i < BG_BLOCKS/4/THREADS_PER_BLOCK; i++) {   // 4 iters
            float4 x = pbg[t + i*THREADS_PER_BLOCK];
            a += x.x + x.y + x.z + x.w;
        }
        float p = 0.f;
        if (t < BATCH/4) {                                           // 256 lanes
            float4 x = ppos[t];
            p = x.x + x.y + x.z + x.w;
        }
        a = warp_sum(a);
        p = warp_sum(p);
        __shared__ float sb[WARPS_PER_BLOCK], sp[WARPS_PER_BLOCK];
        if (lane == 0) { sb[warp] = a; sp[warp] = p; }
        __syncthreads();
        if (threadIdx.x == 0) {
            float bgsum = 0.f, possum = 0.f;
            #pragma unroll
            for (int w = 0; w < WARPS_PER_BLOCK; w++) { bgsum += sb[w]; possum += sp[w]; }
            out[0] = log1pf(bgsum / possum);
            g_done_count = 0;   // reset for next graph replay
        }
    }
}

extern "C" void kernel_launch(void* const* d_in, const int* in_sizes, int n_in,
                              void* d_out, int out_size)
{
    const float* fg_img = (const float*)d_in[0];   // [B, D]
    const float* fg_pro = (const float*)d_in[1];   // [B, D]
    const float* bg_pro = (const float*)d_in[2];   // [B, N, D]
    float* out = (float*)d_out;

    bg_kernel<<<BG_BLOCKS, THREADS_PER_BLOCK>>>(fg_img, fg_pro, bg_pro, out);
}